// round 13
// baseline (speedup 1.0000x reference)
#include <cuda_runtime.h>
#include <cuda_bf16.h>
#include <cstdint>
#include <cstddef>

// ---------------- problem constants ----------------
#define MAXPTS 300000
#define CC 128            // channels
#define NSC 4             // number of scales
#define COORDN 512u
#define NSLOTS (1u<<19)   // hash slots per scale
#define SLOT_MASK (NSLOTS-1u)
#define EMPTY_KEY 0xFFFFFFFFu
#define INV_DID 0xFFFFFFFFu
#define MAXB 150016       // worst-case non-singleton buckets per scale (M/2)
#define EPSV 1e-5f
#define SLOPEV 0.01f

#define TM 64             // GEMM rows per CTA tile (2 CTAs/SM)
#define SP 136            // smem row stride in bf16 (272B -> conflict-free)

// ---------------- device scratch (zero-init .bss) ----------------
__device__ unsigned g_keys[NSC * NSLOTS];
__device__ int      g_counts[NSC * NSLOTS];
__device__ unsigned g_dense[NSC * NSLOTS];               // slot -> dense bucket id (or INV)
__device__ int      g_ccount[NSC * MAXB];                // dense id -> count
__device__ float    g_csums[(size_t)NSC * MAXB * CC];    // compact sums (~54MB live; L2!)
__device__ unsigned g_slotflag[NSC * MAXPTS];            // did | singleton<<31
__device__ int      g_list[NSC * MAXPTS];
__device__ int      g_nnz[NSC];
__device__ int      g_nbuckets[NSC];
__device__ float    g_chanSum[NSC * CC];
__device__ float    g_chanSq[NSC * CC];
__device__ float    g_A[NSC * CC];
__device__ float    g_Bc[NSC * CC];
__device__ float    g_sv[NSC * CC];
__device__ __nv_bfloat16 g_WtHi[NSC * CC * CC];          // Wt[n][k] = bf16_hi(W[k][n])
__device__ __nv_bfloat16 g_WtLo[NSC * CC * CC];

__device__ __forceinline__ unsigned hash32(unsigned x) {
    x ^= x >> 16; x *= 0x7feb352dU;
    x ^= x >> 15; x *= 0x846ca68bU;
    x ^= x >> 16;
    return x;
}

__device__ __forceinline__ void mma_bf16(float& d0, float& d1, float& d2, float& d3,
                                         uint32_t a0, uint32_t a1, uint32_t a2, uint32_t a3,
                                         uint32_t b0, uint32_t b1) {
    asm volatile(
        "mma.sync.aligned.m16n8k16.row.col.f32.bf16.bf16.f32 "
        "{%0,%1,%2,%3}, {%4,%5,%6,%7}, {%8,%9}, {%0,%1,%2,%3};\n"
        : "+f"(d0), "+f"(d1), "+f"(d2), "+f"(d3)
        : "r"(a0), "r"(a1), "r"(a2), "r"(a3), "r"(b0), "r"(b1));
}

__device__ __forceinline__ void ldsm_x4(uint32_t& r0, uint32_t& r1, uint32_t& r2,
                                        uint32_t& r3, uint32_t addr) {
    asm volatile("ldmatrix.sync.aligned.m8n8.x4.shared.b16 {%0,%1,%2,%3}, [%4];"
                 : "=r"(r0), "=r"(r1), "=r"(r2), "=r"(r3) : "r"(addr));
}

__device__ __forceinline__ void red_v4(float* dst, float4 v) {
    asm volatile("red.global.add.v4.f32 [%0], {%1,%2,%3,%4};"
                 :: "l"(dst), "f"(v.x), "f"(v.y), "f"(v.z), "f"(v.w) : "memory");
}

// ---------------- kernels ----------------

// fused clear + W split-prep (independent index ranges)
__global__ void k_clear_prep(const float* __restrict__ W) {
    unsigned i = blockIdx.x * blockDim.x + threadIdx.x;
    if (i < NSC * NSLOTS) { g_keys[i] = EMPTY_KEY; g_counts[i] = 0; }
    if (i < NSC) { g_nnz[i] = 0; g_nbuckets[i] = 0; }
    if (i < NSC * CC * CC) {
        int s = i >> 14, rem = i & 16383, n = rem >> 7, k = rem & 127;
        float v = W[(size_t)s * CC * CC + k * CC + n];
        __nv_bfloat16 hi = __float2bfloat16_rn(v);
        __nv_bfloat16 lo = __float2bfloat16_rn(v - __bfloat162float(hi));
        g_WtHi[i] = hi;
        g_WtLo[i] = lo;
    }
}

// one thread per point; probes all 4 scale tables (idx loaded once, 4-way ILP)
__global__ void k_build_all(const int* __restrict__ idx, int M) {
    int p = blockIdx.x * blockDim.x + threadIdx.x;
    if (p >= M) return;
    int4 q = *(const int4*)(idx + p * 4);
    unsigned b = (unsigned)q.x;
    #pragma unroll
    for (int s = 0; s < NSC; s++) {
        int shift = s + 1;                       // scales 2,4,8,16
        unsigned cx = (unsigned)q.y >> shift;
        unsigned cy = (unsigned)q.z >> shift;
        unsigned cz = (unsigned)q.w >> shift;
        unsigned key = ((b * COORDN + cx) * COORDN + cy) * COORDN + cz;
        unsigned slot = hash32(key) & SLOT_MASK;
        unsigned* keys = g_keys + s * NSLOTS;
        while (true) {
            unsigned prev = atomicCAS(&keys[slot], EMPTY_KEY, key);
            if (prev == EMPTY_KEY || prev == key) break;
            slot = (slot + 1u) & SLOT_MASK;
        }
        g_slotflag[s * MAXPTS + p] = slot;
        atomicAdd(&g_counts[s * NSLOTS + slot], 1);
    }
}

// dense-id assignment: one thread per slot, block-aggregated counter.
__global__ void k_assign() {
    __shared__ int s_cnt, s_base;
    int s = blockIdx.y;
    int tid = threadIdx.x;
    unsigned i = blockIdx.x * blockDim.x + tid;
    if (tid == 0) s_cnt = 0;
    __syncthreads();
    int c = g_counts[s * NSLOTS + i];
    int pos = -1;
    if (c > 1) pos = atomicAdd(&s_cnt, 1);
    __syncthreads();
    if (tid == 0 && s_cnt > 0) s_base = atomicAdd(&g_nbuckets[s], s_cnt);
    __syncthreads();
    if (c > 1) {
        unsigned did = (unsigned)(s_base + pos);
        g_dense[s * NSLOTS + i] = did;
        g_ccount[s * MAXB + did] = c;
    } else {
        g_dense[s * NSLOTS + i] = INV_DID;
    }
}

// fused flag + accumulate, all scales: blockIdx.y = scale, 8 threads per point.
__global__ void k_flagaccum_all(const float* __restrict__ feats, int M) {
    __shared__ int s_cnt, s_base;
    __shared__ int s_pts[32];
    int s = blockIdx.y;
    int tid = threadIdx.x;
    if (tid == 0) s_cnt = 0;
    __syncthreads();

    int g = blockIdx.x * blockDim.x + tid;
    int p = g >> 3;
    int li = g & 7;
    if (p < M) {
        unsigned slot = g_slotflag[s * MAXPTS + p];
        unsigned did = g_dense[s * NSLOTS + slot];
        if (did != INV_DID) {
            if (li == 0) {
                int pos = atomicAdd(&s_cnt, 1);
                s_pts[pos] = p;
                g_slotflag[s * MAXPTS + p] = did;
            }
            const float4* src = (const float4*)(feats + (size_t)p * CC + li * 16);
            float* dst = g_csums + ((size_t)s * MAXB + did) * CC + li * 16;
            #pragma unroll
            for (int j = 0; j < 4; j++) red_v4(dst + j * 4, src[j]);
        } else if (li == 0) {
            g_slotflag[s * MAXPTS + p] = slot | 0x80000000u;
        }
    }
    __syncthreads();
    int cnt = s_cnt;
    if (tid == 0 && cnt > 0) s_base = atomicAdd(&g_nnz[s], cnt);
    __syncthreads();
    if (tid < cnt) g_list[s * MAXPTS + s_base + tid] = s_pts[tid];
}

// re-zero the used compact csums region: SEQUENTIAL, coalesced
__global__ void k_zero_all() {
    int s = blockIdx.y;
    int n4 = g_nbuckets[s] * (CC / 4);
    float4* base = (float4*)(g_csums + (size_t)s * MAXB * CC);
    float4 z = make_float4(0.f, 0.f, 0.f, 0.f);
    for (int i = blockIdx.x * blockDim.x + threadIdx.x; i < n4;
         i += gridDim.x * blockDim.x)
        base[i] = z;
}

// ---- HMMA bf16 split GEMM, all scales (blockIdx.y = scale) ----
// TM=64 rows, 128 threads, 104KB smem -> 2 CTAs/SM for phase overlap.
// Os = Ahi + Alo, Wt = Bhi + Blo ; acc += AhiBhi + AhiBlo + AloBhi (fp32)
__global__ __launch_bounds__(128, 2)
void k_gemm_all(const float* __restrict__ feats, const float* __restrict__ bvec,
                float* __restrict__ out) {
    int s = blockIdx.y;
    int nnz = g_nnz[s];
    int base = blockIdx.x * TM;
    if (base >= nnz) return;

    extern __shared__ __nv_bfloat16 sm[];
    __nv_bfloat16* AHI = sm;                   // [64][SP]
    __nv_bfloat16* ALO = sm + TM * SP;
    __nv_bfloat16* BHI = sm + 2 * TM * SP;     // [128][SP]
    __nv_bfloat16* BLO = sm + 2 * TM * SP + 128 * SP;
    __shared__ float bsum[CC], bsq[CC], bsh[CC];

    int tid = threadIdx.x;
    int wid = tid >> 5;     // 0..3
    int lane = tid & 31;

    if (tid < CC) {
        bsum[tid] = 0.f; bsq[tid] = 0.f;
        bsh[tid] = bvec[s * CC + tid];
    }

    // --- stage B: 1 thread per n-row, full 128 k (uint4 copies) ---
    {
        int n = tid;
        const uint4* whi = (const uint4*)(g_WtHi + (size_t)s * CC * CC + n * CC);
        const uint4* wlo = (const uint4*)(g_WtLo + (size_t)s * CC * CC + n * CC);
        uint4* dh = (uint4*)(BHI + n * SP);
        uint4* dl = (uint4*)(BLO + n * SP);
        #pragma unroll
        for (int kk = 0; kk < 16; kk++) { dh[kk] = whi[kk]; dl[kk] = wlo[kk]; }
    }

    // --- stage A (Os hi/lo): 2 threads per m-row, 64 k each ---
    {
        int rr = tid >> 1, kh = (tid & 1) << 6;
        int li = base + rr;
        bool valid = li < nnz;
        int p = valid ? g_list[s * MAXPTS + li] : 0;
        unsigned did = valid ? g_slotflag[s * MAXPTS + p] : 0u;
        float invc = valid ? 1.0f / (float)g_ccount[s * MAXB + did] : 0.f;
        const float* fp = feats + (size_t)p * CC + kh;
        const float* sp = g_csums + ((size_t)s * MAXB + did) * CC + kh;
        uint32_t* dh = (uint32_t*)(AHI + rr * SP + kh);
        uint32_t* dl = (uint32_t*)(ALO + rr * SP + kh);
        #pragma unroll 4
        for (int k = 0; k < 64; k += 4) {
            float4 f = valid ? *(const float4*)(fp + k) : make_float4(0.f, 0.f, 0.f, 0.f);
            float4 sv = valid ? *(const float4*)(sp + k) : make_float4(0.f, 0.f, 0.f, 0.f);
            float o0 = (f.x - sv.x * invc) * f.x;
            float o1 = (f.y - sv.y * invc) * f.y;
            float o2 = (f.z - sv.z * invc) * f.z;
            float o3 = (f.w - sv.w * invc) * f.w;
            __nv_bfloat162 h0 = __floats2bfloat162_rn(o0, o1);
            __nv_bfloat162 h1 = __floats2bfloat162_rn(o2, o3);
            __nv_bfloat162 l0 = __floats2bfloat162_rn(o0 - __bfloat162float(h0.x),
                                                      o1 - __bfloat162float(h0.y));
            __nv_bfloat162 l1 = __floats2bfloat162_rn(o2 - __bfloat162float(h1.x),
                                                      o3 - __bfloat162float(h1.y));
            uint2 hv, lv;
            hv.x = *(uint32_t*)&h0; hv.y = *(uint32_t*)&h1;
            lv.x = *(uint32_t*)&l0; lv.y = *(uint32_t*)&l1;
            *(uint2*)(dh + (k >> 1)) = hv;
            *(uint2*)(dl + (k >> 1)) = lv;
        }
    }
    __syncthreads();

    // --- mma mainloop: each warp owns 16 rows x 128 cols; ldmatrix operands ---
    float acc[16][4];
    #pragma unroll
    for (int n = 0; n < 16; n++)
        #pragma unroll
        for (int j = 0; j < 4; j++) acc[n][j] = 0.f;

    uint32_t sAHI = (uint32_t)__cvta_generic_to_shared(AHI);
    uint32_t sALO = (uint32_t)__cvta_generic_to_shared(ALO);
    uint32_t sBHI = (uint32_t)__cvta_generic_to_shared(BHI);
    uint32_t sBLO = (uint32_t)__cvta_generic_to_shared(BLO);

    uint32_t aoff = (uint32_t)((wid * 16 + (lane & 7) + ((lane >> 3) & 1) * 8) * SP
                               + (lane >> 4) * 8) * 2u;
    uint32_t boff = (uint32_t)(((lane & 7) + ((lane >> 4) & 1) * 8) * SP
                               + ((lane >> 3) & 1) * 8) * 2u;

    #pragma unroll
    for (int kt = 0; kt < 8; kt++) {
        uint32_t k0b = (uint32_t)kt * 32u;           // 16 bf16 = 32 bytes
        uint32_t ah0, ah1, ah2, ah3, al0, al1, al2, al3;
        ldsm_x4(ah0, ah1, ah2, ah3, sAHI + aoff + k0b);
        ldsm_x4(al0, al1, al2, al3, sALO + aoff + k0b);
        #pragma unroll
        for (int ntp = 0; ntp < 8; ntp++) {
            uint32_t bo = boff + (uint32_t)ntp * (16u * SP * 2u) + k0b;
            uint32_t bh0, bh1, bh2, bh3, bl0, bl1, bl2, bl3;
            ldsm_x4(bh0, bh1, bh2, bh3, sBHI + bo);
            ldsm_x4(bl0, bl1, bl2, bl3, sBLO + bo);
            int n0 = 2 * ntp, n1 = 2 * ntp + 1;
            mma_bf16(acc[n0][0], acc[n0][1], acc[n0][2], acc[n0][3],
                     ah0, ah1, ah2, ah3, bh0, bh1);
            mma_bf16(acc[n0][0], acc[n0][1], acc[n0][2], acc[n0][3],
                     ah0, ah1, ah2, ah3, bl0, bl1);
            mma_bf16(acc[n0][0], acc[n0][1], acc[n0][2], acc[n0][3],
                     al0, al1, al2, al3, bh0, bh1);
            mma_bf16(acc[n1][0], acc[n1][1], acc[n1][2], acc[n1][3],
                     ah0, ah1, ah2, ah3, bh2, bh3);
            mma_bf16(acc[n1][0], acc[n1][1], acc[n1][2], acc[n1][3],
                     ah0, ah1, ah2, ah3, bl2, bl3);
            mma_bf16(acc[n1][0], acc[n1][1], acc[n1][2], acc[n1][3],
                     al0, al1, al2, al3, bh2, bh3);
        }
    }

    // --- epilogue: h = acc + b; store raw h; per-channel sum/sumsq ---
    int r0 = base + wid * 16 + (lane >> 2);
    int r1 = r0 + 8;
    bool v0 = r0 < nnz, v1 = r1 < nnz;
    int p0 = v0 ? g_list[s * MAXPTS + r0] : 0;
    int p1 = v1 ? g_list[s * MAXPTS + r1] : 0;
    float* o0 = out + ((size_t)p0 * NSC + s) * CC;
    float* o1 = out + ((size_t)p1 * NSC + s) * CC;

    #pragma unroll
    for (int n = 0; n < 16; n++) {
        int c0 = n * 8 + ((lane & 3) << 1);
        float bx = bsh[c0], by = bsh[c0 + 1];
        float h0x = acc[n][0] + bx, h0y = acc[n][1] + by;
        float h1x = acc[n][2] + bx, h1y = acc[n][3] + by;
        if (v0) *(float2*)(o0 + c0) = make_float2(h0x, h0y);
        if (v1) *(float2*)(o1 + c0) = make_float2(h1x, h1y);
        float sx = (v0 ? h0x : 0.f) + (v1 ? h1x : 0.f);
        float sy = (v0 ? h0y : 0.f) + (v1 ? h1y : 0.f);
        float qx = (v0 ? h0x * h0x : 0.f) + (v1 ? h1x * h1x : 0.f);
        float qy = (v0 ? h0y * h0y : 0.f) + (v1 ? h1y * h1y : 0.f);
        #pragma unroll
        for (int o = 4; o < 32; o <<= 1) {
            sx += __shfl_xor_sync(0xFFFFFFFFu, sx, o);
            sy += __shfl_xor_sync(0xFFFFFFFFu, sy, o);
            qx += __shfl_xor_sync(0xFFFFFFFFu, qx, o);
            qy += __shfl_xor_sync(0xFFFFFFFFu, qy, o);
        }
        if (lane < 4) {
            atomicAdd(&bsum[c0],     sx);
            atomicAdd(&bsum[c0 + 1], sy);
            atomicAdd(&bsq[c0],      qx);
            atomicAdd(&bsq[c0 + 1],  qy);
        }
    }
    __syncthreads();
    if (tid < CC) {
        atomicAdd(&g_chanSum[s * CC + tid], bsum[tid]);
        atomicAdd(&g_chanSq[s * CC + tid],  bsq[tid]);
    }
}

// all scales in one block: tid = s*128 + c
__global__ void k_finalize_all(const float* __restrict__ bvec, const float* __restrict__ gamma,
                               const float* __restrict__ beta, int M) {
    int t = threadIdx.x;           // 512 threads
    int s = t >> 7, c = t & 127;
    int i = s * CC + c;
    float bc = bvec[i];
    float rem = (float)(M - g_nnz[s]);
    float sum = g_chanSum[i] + rem * bc;
    float sq  = g_chanSq[i]  + rem * bc * bc;
    float mu  = sum / (float)M;
    float var = sq / (float)M - mu * mu;
    float A = rsqrtf(var + EPSV) * gamma[i];
    float B = beta[i] - mu * A;
    g_A[i]  = A;
    g_Bc[i] = B;
    float tv = bc * A + B;
    g_sv[i] = tv > 0.f ? tv : SLOPEV * tv;
    g_chanSum[i] = 0.f;
    g_chanSq[i]  = 0.f;
}

// fused normalize over all 4 scales: one warp per point, 2KB contiguous row
__global__ __launch_bounds__(256)
void k_norm_all(float* __restrict__ out, int M) {
    __shared__ float sA[NSC * CC], sB[NSC * CC], sSV[NSC * CC];
    int tid = threadIdx.x;
    for (int i = tid; i < NSC * CC; i += 256) {
        sA[i] = g_A[i]; sB[i] = g_Bc[i]; sSV[i] = g_sv[i];
    }
    __syncthreads();

    int g = blockIdx.x * blockDim.x + threadIdx.x;
    int p = g >> 5;
    if (p >= M) return;
    int lane = g & 31;
    int c4 = lane << 2;

    unsigned myf = (lane < NSC) ? g_slotflag[lane * MAXPTS + p] : 0u;
    float* op = out + (size_t)p * NSC * CC;

    #pragma unroll
    for (int s = 0; s < NSC; s++) {
        unsigned sing = __shfl_sync(0xFFFFFFFFu, myf, s) & 0x80000000u;
        float* q = op + s * CC + c4;
        float4 v;
        if (sing) {
            v = *(const float4*)(sSV + s * CC + c4);
        } else {
            float4 h = *(const float4*)q;
            const float* Ap = sA + s * CC + c4;
            const float* Bp = sB + s * CC + c4;
            v.x = h.x * Ap[0] + Bp[0];
            v.y = h.y * Ap[1] + Bp[1];
            v.z = h.z * Ap[2] + Bp[2];
            v.w = h.w * Ap[3] + Bp[3];
            v.x = v.x > 0.f ? v.x : SLOPEV * v.x;
            v.y = v.y > 0.f ? v.y : SLOPEV * v.y;
            v.z = v.z > 0.f ? v.z : SLOPEV * v.z;
            v.w = v.w > 0.f ? v.w : SLOPEV * v.w;
        }
        *(float4*)q = v;
    }
}

// ---------------- launcher ----------------
extern "C" void kernel_launch(void* const* d_in, const int* in_sizes, int n_in,
                              void* d_out, int out_size) {
    const float* feats = (const float*)d_in[0];
    const int*   idx   = (const int*)d_in[1];
    const float* W     = (const float*)d_in[2];
    const float* bvec  = (const float*)d_in[3];
    const float* gamma = (const float*)d_in[4];
    const float* beta  = (const float*)d_in[5];
    float* out = (float*)d_out;

    int M = in_sizes[0] / CC;   // 300000

    size_t smem_mma = (size_t)(2 * TM + 2 * 128) * SP * sizeof(__nv_bfloat16);  // 104448 B
    cudaFuncSetAttribute(k_gemm_all, cudaFuncAttributeMaxDynamicSharedMemorySize,
                         (int)smem_mma);

    int grid_slots = (NSC * NSLOTS + 255) / 256;
    int grid_pts   = (M + 255) / 256;
    int grid_8     = (M * 8 + 255) / 256;      // 9375
    int grid_warp  = (M * 32 + 255) / 256;     // 37500
    int grid_gemm  = (M + TM - 1) / TM;        // 4688

    dim3 g8(grid_8, NSC);
    dim3 ggemm(grid_gemm, NSC);
    dim3 gassign(NSLOTS / 256, NSC);
    dim3 gzero(512, NSC);

    k_clear_prep<<<grid_slots, 256>>>(W);
    k_build_all<<<grid_pts, 256>>>(idx, M);
    k_assign<<<gassign, 256>>>();
    k_flagaccum_all<<<g8, 256>>>(feats, M);
    k_gemm_all<<<ggemm, 128, smem_mma>>>(feats, bvec, out);
    k_zero_all<<<gzero, 256>>>();
    k_finalize_all<<<1, 512>>>(bvec, gamma, beta, M);
    k_norm_all<<<grid_warp, 256>>>(out, M);
}

// round 14
// speedup vs baseline: 1.1591x; 1.1591x over previous
#include <cuda_runtime.h>
#include <cuda_bf16.h>
#include <cstdint>
#include <cstddef>

// ---------------- problem constants ----------------
#define MAXPTS 300000
#define CC 128            // channels
#define NSC 4             // number of scales
#define COORDN 512u
#define NSLOTS (1u<<19)   // hash slots per scale
#define SLOT_MASK (NSLOTS-1u)
#define EMPTY_KEY 0xFFFFFFFFu
#define INV_DID 0xFFFFFFFFu
#define MAXB 150016       // worst-case non-singleton buckets per scale (M/2)
#define EPSV 1e-5f
#define SLOPEV 0.01f

#define TM 128            // GEMM rows per CTA tile (R12 config — best)
#define SP 136            // smem row stride in bf16 (272B -> conflict-free)

// ---------------- device scratch (zero-init .bss) ----------------
__device__ unsigned g_keys[NSC * NSLOTS];
__device__ int      g_counts[NSC * NSLOTS];
__device__ unsigned g_dense[NSC * NSLOTS];               // slot -> dense bucket id (or INV)
__device__ int      g_ccount[NSC * MAXB];                // dense id -> count
__device__ float    g_csums[(size_t)NSC * MAXB * CC];    // compact sums (~54MB live; L2!)
__device__ unsigned g_slotflag[NSC * MAXPTS];            // did | singleton<<31
__device__ int      g_list[NSC * MAXPTS];
__device__ int      g_nnz[NSC];
__device__ int      g_nbuckets[NSC];
__device__ float    g_chanSum[NSC * CC];
__device__ float    g_chanSq[NSC * CC];
__device__ float    g_A[NSC * CC];
__device__ float    g_Bc[NSC * CC];
__device__ float    g_sv[NSC * CC];
__device__ __nv_bfloat16 g_WtHi[NSC * CC * CC];          // Wt[n][k] = bf16_hi(W[k][n])
__device__ __nv_bfloat16 g_WtLo[NSC * CC * CC];

__device__ __forceinline__ unsigned hash32(unsigned x) {
    x ^= x >> 16; x *= 0x7feb352dU;
    x ^= x >> 15; x *= 0x846ca68bU;
    x ^= x >> 16;
    return x;
}

__device__ __forceinline__ void mma_bf16(float& d0, float& d1, float& d2, float& d3,
                                         uint32_t a0, uint32_t a1, uint32_t a2, uint32_t a3,
                                         uint32_t b0, uint32_t b1) {
    asm volatile(
        "mma.sync.aligned.m16n8k16.row.col.f32.bf16.bf16.f32 "
        "{%0,%1,%2,%3}, {%4,%5,%6,%7}, {%8,%9}, {%0,%1,%2,%3};\n"
        : "+f"(d0), "+f"(d1), "+f"(d2), "+f"(d3)
        : "r"(a0), "r"(a1), "r"(a2), "r"(a3), "r"(b0), "r"(b1));
}

__device__ __forceinline__ void ldsm_x4(uint32_t& r0, uint32_t& r1, uint32_t& r2,
                                        uint32_t& r3, uint32_t addr) {
    asm volatile("ldmatrix.sync.aligned.m8n8.x4.shared.b16 {%0,%1,%2,%3}, [%4];"
                 : "=r"(r0), "=r"(r1), "=r"(r2), "=r"(r3) : "r"(addr));
}

__device__ __forceinline__ void red_v4(float* dst, float4 v) {
    asm volatile("red.global.add.v4.f32 [%0], {%1,%2,%3,%4};"
                 :: "l"(dst), "f"(v.x), "f"(v.y), "f"(v.z), "f"(v.w) : "memory");
}

// ---------------- kernels ----------------

// fused clear + W split-prep (independent index ranges)
__global__ void k_clear_prep(const float* __restrict__ W) {
    unsigned i = blockIdx.x * blockDim.x + threadIdx.x;
    if (i < NSC * NSLOTS) { g_keys[i] = EMPTY_KEY; g_counts[i] = 0; }
    if (i < NSC) { g_nnz[i] = 0; g_nbuckets[i] = 0; }
    if (i < NSC * CC * CC) {
        int s = i >> 14, rem = i & 16383, n = rem >> 7, k = rem & 127;
        float v = W[(size_t)s * CC * CC + k * CC + n];
        __nv_bfloat16 hi = __float2bfloat16_rn(v);
        __nv_bfloat16 lo = __float2bfloat16_rn(v - __bfloat162float(hi));
        g_WtHi[i] = hi;
        g_WtLo[i] = lo;
    }
}

// one thread per point; probes all 4 scale tables (idx loaded once, 4-way ILP)
__global__ void k_build_all(const int* __restrict__ idx, int M) {
    int p = blockIdx.x * blockDim.x + threadIdx.x;
    if (p >= M) return;
    int4 q = *(const int4*)(idx + p * 4);
    unsigned b = (unsigned)q.x;
    #pragma unroll
    for (int s = 0; s < NSC; s++) {
        int shift = s + 1;                       // scales 2,4,8,16
        unsigned cx = (unsigned)q.y >> shift;
        unsigned cy = (unsigned)q.z >> shift;
        unsigned cz = (unsigned)q.w >> shift;
        unsigned key = ((b * COORDN + cx) * COORDN + cy) * COORDN + cz;
        unsigned slot = hash32(key) & SLOT_MASK;
        unsigned* keys = g_keys + s * NSLOTS;
        while (true) {
            unsigned prev = atomicCAS(&keys[slot], EMPTY_KEY, key);
            if (prev == EMPTY_KEY || prev == key) break;
            slot = (slot + 1u) & SLOT_MASK;
        }
        g_slotflag[s * MAXPTS + p] = slot;
        atomicAdd(&g_counts[s * NSLOTS + slot], 1);
    }
}

// dense-id assignment: one thread per slot, block-aggregated counter.
__global__ void k_assign() {
    __shared__ int s_cnt, s_base;
    int s = blockIdx.y;
    int tid = threadIdx.x;
    unsigned i = blockIdx.x * blockDim.x + tid;
    if (tid == 0) s_cnt = 0;
    __syncthreads();
    int c = g_counts[s * NSLOTS + i];
    int pos = -1;
    if (c > 1) pos = atomicAdd(&s_cnt, 1);
    __syncthreads();
    if (tid == 0 && s_cnt > 0) s_base = atomicAdd(&g_nbuckets[s], s_cnt);
    __syncthreads();
    if (c > 1) {
        unsigned did = (unsigned)(s_base + pos);
        g_dense[s * NSLOTS + i] = did;
        g_ccount[s * MAXB + did] = c;
    } else {
        g_dense[s * NSLOTS + i] = INV_DID;
    }
}

// fused flag + accumulate, ONE pass over points (all scales inside):
// 8 threads/point; feats loaded once; 4-way MLP on the slot/dense gathers.
__global__ void k_flagaccum_all(const float* __restrict__ feats, int M) {
    __shared__ int s_cnt[NSC], s_base[NSC];
    __shared__ int s_pts[NSC][32];               // 32 points per 256-thread block
    int tid = threadIdx.x;
    if (tid < NSC) s_cnt[tid] = 0;
    __syncthreads();

    int g = blockIdx.x * blockDim.x + tid;
    int p = g >> 3;
    int li = g & 7;
    if (p < M) {
        // batch the 4 slotflag loads (independent; MLP)
        unsigned slot[NSC];
        #pragma unroll
        for (int s = 0; s < NSC; s++) slot[s] = g_slotflag[s * MAXPTS + p];
        // batch the 4 dense gathers
        unsigned did[NSC];
        #pragma unroll
        for (int s = 0; s < NSC; s++) did[s] = g_dense[s * NSLOTS + slot[s]];

        bool any = false;
        #pragma unroll
        for (int s = 0; s < NSC; s++) {
            if (did[s] != INV_DID) {
                any = true;
                if (li == 0) {
                    int pos = atomicAdd(&s_cnt[s], 1);
                    s_pts[s][pos] = p;
                    g_slotflag[s * MAXPTS + p] = did[s];
                }
            } else if (li == 0) {
                g_slotflag[s * MAXPTS + p] = slot[s] | 0x80000000u;
            }
        }
        if (any) {
            const float4* src = (const float4*)(feats + (size_t)p * CC + li * 16);
            float4 v0 = src[0], v1 = src[1], v2 = src[2], v3 = src[3];
            #pragma unroll
            for (int s = 0; s < NSC; s++) {
                if (did[s] != INV_DID) {
                    float* dst = g_csums + ((size_t)s * MAXB + did[s]) * CC + li * 16;
                    red_v4(dst + 0,  v0);
                    red_v4(dst + 4,  v1);
                    red_v4(dst + 8,  v2);
                    red_v4(dst + 12, v3);
                }
            }
        }
    }
    __syncthreads();
    if (tid < NSC && s_cnt[tid] > 0)
        s_base[tid] = atomicAdd(&g_nnz[tid], s_cnt[tid]);
    __syncthreads();
    if (tid < NSC * 32) {
        int s = tid >> 5, j = tid & 31;
        if (j < s_cnt[s]) g_list[s * MAXPTS + s_base[s] + j] = s_pts[s][j];
    }
}

// re-zero the used compact csums region: SEQUENTIAL, coalesced
__global__ void k_zero_all() {
    int s = blockIdx.y;
    int n4 = g_nbuckets[s] * (CC / 4);
    float4* base = (float4*)(g_csums + (size_t)s * MAXB * CC);
    float4 z = make_float4(0.f, 0.f, 0.f, 0.f);
    for (int i = blockIdx.x * blockDim.x + threadIdx.x; i < n4;
         i += gridDim.x * blockDim.x)
        base[i] = z;
}

// ---- HMMA bf16 split GEMM, all scales (blockIdx.y = scale) — R12 config ----
// Os = Ahi + Alo, Wt = Bhi + Blo ; acc += AhiBhi + AhiBlo + AloBhi (fp32)
__global__ __launch_bounds__(256, 1)
void k_gemm_all(const float* __restrict__ feats, const float* __restrict__ bvec,
                float* __restrict__ out) {
    int s = blockIdx.y;
    int nnz = g_nnz[s];
    int base = blockIdx.x * TM;
    if (base >= nnz) return;

    extern __shared__ __nv_bfloat16 sm[];
    __nv_bfloat16* AHI = sm;                 // [128][SP]
    __nv_bfloat16* ALO = sm + 128 * SP;
    __nv_bfloat16* BHI = sm + 2 * 128 * SP;
    __nv_bfloat16* BLO = sm + 3 * 128 * SP;
    __shared__ float bsum[CC], bsq[CC], bsh[CC];

    int tid = threadIdx.x;
    int wid = tid >> 5;
    int lane = tid & 31;

    if (tid < CC) {
        bsum[tid] = 0.f; bsq[tid] = 0.f;
        bsh[tid] = bvec[s * CC + tid];
    }

    // --- stage B: 2 threads per n-row, 64 k each (uint4 copies) ---
    {
        int n = tid >> 1, kh = (tid & 1) << 6;
        const uint4* whi = (const uint4*)(g_WtHi + (size_t)s * CC * CC + n * CC + kh);
        const uint4* wlo = (const uint4*)(g_WtLo + (size_t)s * CC * CC + n * CC + kh);
        uint4* dh = (uint4*)(BHI + n * SP + kh);
        uint4* dl = (uint4*)(BLO + n * SP + kh);
        #pragma unroll
        for (int kk = 0; kk < 8; kk++) { dh[kk] = whi[kk]; dl[kk] = wlo[kk]; }
    }

    // --- stage A (Os hi/lo): 2 threads per m-row, 64 k each ---
    {
        int rr = tid >> 1, kh = (tid & 1) << 6;
        int li = base + rr;
        bool valid = li < nnz;
        int p = valid ? g_list[s * MAXPTS + li] : 0;
        unsigned did = valid ? g_slotflag[s * MAXPTS + p] : 0u;
        float invc = valid ? 1.0f / (float)g_ccount[s * MAXB + did] : 0.f;
        const float* fp = feats + (size_t)p * CC + kh;
        const float* sp = g_csums + ((size_t)s * MAXB + did) * CC + kh;
        uint32_t* dh = (uint32_t*)(AHI + rr * SP + kh);
        uint32_t* dl = (uint32_t*)(ALO + rr * SP + kh);
        #pragma unroll 4
        for (int k = 0; k < 64; k += 4) {
            float4 f = valid ? *(const float4*)(fp + k) : make_float4(0.f, 0.f, 0.f, 0.f);
            float4 sv = valid ? *(const float4*)(sp + k) : make_float4(0.f, 0.f, 0.f, 0.f);
            float o0 = (f.x - sv.x * invc) * f.x;
            float o1 = (f.y - sv.y * invc) * f.y;
            float o2 = (f.z - sv.z * invc) * f.z;
            float o3 = (f.w - sv.w * invc) * f.w;
            __nv_bfloat162 h0 = __floats2bfloat162_rn(o0, o1);
            __nv_bfloat162 h1 = __floats2bfloat162_rn(o2, o3);
            __nv_bfloat162 l0 = __floats2bfloat162_rn(o0 - __bfloat162float(h0.x),
                                                      o1 - __bfloat162float(h0.y));
            __nv_bfloat162 l1 = __floats2bfloat162_rn(o2 - __bfloat162float(h1.x),
                                                      o3 - __bfloat162float(h1.y));
            uint2 hv, lv;
            hv.x = *(uint32_t*)&h0; hv.y = *(uint32_t*)&h1;
            lv.x = *(uint32_t*)&l0; lv.y = *(uint32_t*)&l1;
            *(uint2*)(dh + (k >> 1)) = hv;
            *(uint2*)(dl + (k >> 1)) = lv;
        }
    }
    __syncthreads();

    // --- mma mainloop: each warp owns 16 rows x 128 cols; ldmatrix operands ---
    float acc[16][4];
    #pragma unroll
    for (int n = 0; n < 16; n++)
        #pragma unroll
        for (int j = 0; j < 4; j++) acc[n][j] = 0.f;

    uint32_t sAHI = (uint32_t)__cvta_generic_to_shared(AHI);
    uint32_t sALO = (uint32_t)__cvta_generic_to_shared(ALO);
    uint32_t sBHI = (uint32_t)__cvta_generic_to_shared(BHI);
    uint32_t sBLO = (uint32_t)__cvta_generic_to_shared(BLO);

    uint32_t aoff = (uint32_t)((wid * 16 + (lane & 7) + ((lane >> 3) & 1) * 8) * SP
                               + (lane >> 4) * 8) * 2u;
    uint32_t boff = (uint32_t)(((lane & 7) + ((lane >> 4) & 1) * 8) * SP
                               + ((lane >> 3) & 1) * 8) * 2u;

    #pragma unroll
    for (int kt = 0; kt < 8; kt++) {
        uint32_t k0b = (uint32_t)kt * 32u;           // 16 bf16 = 32 bytes
        uint32_t ah0, ah1, ah2, ah3, al0, al1, al2, al3;
        ldsm_x4(ah0, ah1, ah2, ah3, sAHI + aoff + k0b);
        ldsm_x4(al0, al1, al2, al3, sALO + aoff + k0b);
        #pragma unroll
        for (int ntp = 0; ntp < 8; ntp++) {
            uint32_t bo = boff + (uint32_t)ntp * (16u * SP * 2u) + k0b;
            uint32_t bh0, bh1, bh2, bh3, bl0, bl1, bl2, bl3;
            ldsm_x4(bh0, bh1, bh2, bh3, sBHI + bo);
            ldsm_x4(bl0, bl1, bl2, bl3, sBLO + bo);
            int n0 = 2 * ntp, n1 = 2 * ntp + 1;
            mma_bf16(acc[n0][0], acc[n0][1], acc[n0][2], acc[n0][3],
                     ah0, ah1, ah2, ah3, bh0, bh1);
            mma_bf16(acc[n0][0], acc[n0][1], acc[n0][2], acc[n0][3],
                     ah0, ah1, ah2, ah3, bl0, bl1);
            mma_bf16(acc[n0][0], acc[n0][1], acc[n0][2], acc[n0][3],
                     al0, al1, al2, al3, bh0, bh1);
            mma_bf16(acc[n1][0], acc[n1][1], acc[n1][2], acc[n1][3],
                     ah0, ah1, ah2, ah3, bh2, bh3);
            mma_bf16(acc[n1][0], acc[n1][1], acc[n1][2], acc[n1][3],
                     ah0, ah1, ah2, ah3, bl2, bl3);
            mma_bf16(acc[n1][0], acc[n1][1], acc[n1][2], acc[n1][3],
                     al0, al1, al2, al3, bh2, bh3);
        }
    }

    // --- epilogue: h = acc + b; store raw h; per-channel sum/sumsq ---
    int r0 = base + wid * 16 + (lane >> 2);
    int r1 = r0 + 8;
    bool v0 = r0 < nnz, v1 = r1 < nnz;
    int p0 = v0 ? g_list[s * MAXPTS + r0] : 0;
    int p1 = v1 ? g_list[s * MAXPTS + r1] : 0;
    float* o0 = out + ((size_t)p0 * NSC + s) * CC;
    float* o1 = out + ((size_t)p1 * NSC + s) * CC;

    #pragma unroll
    for (int n = 0; n < 16; n++) {
        int c0 = n * 8 + ((lane & 3) << 1);
        float bx = bsh[c0], by = bsh[c0 + 1];
        float h0x = acc[n][0] + bx, h0y = acc[n][1] + by;
        float h1x = acc[n][2] + bx, h1y = acc[n][3] + by;
        if (v0) *(float2*)(o0 + c0) = make_float2(h0x, h0y);
        if (v1) *(float2*)(o1 + c0) = make_float2(h1x, h1y);
        float sx = (v0 ? h0x : 0.f) + (v1 ? h1x : 0.f);
        float sy = (v0 ? h0y : 0.f) + (v1 ? h1y : 0.f);
        float qx = (v0 ? h0x * h0x : 0.f) + (v1 ? h1x * h1x : 0.f);
        float qy = (v0 ? h0y * h0y : 0.f) + (v1 ? h1y * h1y : 0.f);
        #pragma unroll
        for (int o = 4; o < 32; o <<= 1) {
            sx += __shfl_xor_sync(0xFFFFFFFFu, sx, o);
            sy += __shfl_xor_sync(0xFFFFFFFFu, sy, o);
            qx += __shfl_xor_sync(0xFFFFFFFFu, qx, o);
            qy += __shfl_xor_sync(0xFFFFFFFFu, qy, o);
        }
        if (lane < 4) {
            atomicAdd(&bsum[c0],     sx);
            atomicAdd(&bsum[c0 + 1], sy);
            atomicAdd(&bsq[c0],      qx);
            atomicAdd(&bsq[c0 + 1],  qy);
        }
    }
    __syncthreads();
    if (tid < CC) {
        atomicAdd(&g_chanSum[s * CC + tid], bsum[tid]);
        atomicAdd(&g_chanSq[s * CC + tid],  bsq[tid]);
    }
}

// all scales in one block: tid = s*128 + c
__global__ void k_finalize_all(const float* __restrict__ bvec, const float* __restrict__ gamma,
                               const float* __restrict__ beta, int M) {
    int t = threadIdx.x;           // 512 threads
    int s = t >> 7, c = t & 127;
    int i = s * CC + c;
    float bc = bvec[i];
    float rem = (float)(M - g_nnz[s]);
    float sum = g_chanSum[i] + rem * bc;
    float sq  = g_chanSq[i]  + rem * bc * bc;
    float mu  = sum / (float)M;
    float var = sq / (float)M - mu * mu;
    float A = rsqrtf(var + EPSV) * gamma[i];
    float B = beta[i] - mu * A;
    g_A[i]  = A;
    g_Bc[i] = B;
    float tv = bc * A + B;
    g_sv[i] = tv > 0.f ? tv : SLOPEV * tv;
    g_chanSum[i] = 0.f;
    g_chanSq[i]  = 0.f;
}

// fused normalize over all 4 scales: one warp per point, 2KB contiguous row
__global__ __launch_bounds__(256)
void k_norm_all(float* __restrict__ out, int M) {
    __shared__ float sA[NSC * CC], sB[NSC * CC], sSV[NSC * CC];
    int tid = threadIdx.x;
    for (int i = tid; i < NSC * CC; i += 256) {
        sA[i] = g_A[i]; sB[i] = g_Bc[i]; sSV[i] = g_sv[i];
    }
    __syncthreads();

    int g = blockIdx.x * blockDim.x + threadIdx.x;
    int p = g >> 5;
    if (p >= M) return;
    int lane = g & 31;
    int c4 = lane << 2;

    unsigned myf = (lane < NSC) ? g_slotflag[lane * MAXPTS + p] : 0u;
    float* op = out + (size_t)p * NSC * CC;

    #pragma unroll
    for (int s = 0; s < NSC; s++) {
        unsigned sing = __shfl_sync(0xFFFFFFFFu, myf, s) & 0x80000000u;
        float* q = op + s * CC + c4;
        float4 v;
        if (sing) {
            v = *(const float4*)(sSV + s * CC + c4);
        } else {
            float4 h = *(const float4*)q;
            const float* Ap = sA + s * CC + c4;
            const float* Bp = sB + s * CC + c4;
            v.x = h.x * Ap[0] + Bp[0];
            v.y = h.y * Ap[1] + Bp[1];
            v.z = h.z * Ap[2] + Bp[2];
            v.w = h.w * Ap[3] + Bp[3];
            v.x = v.x > 0.f ? v.x : SLOPEV * v.x;
            v.y = v.y > 0.f ? v.y : SLOPEV * v.y;
            v.z = v.z > 0.f ? v.z : SLOPEV * v.z;
            v.w = v.w > 0.f ? v.w : SLOPEV * v.w;
        }
        *(float4*)q = v;
    }
}

// ---------------- launcher ----------------
extern "C" void kernel_launch(void* const* d_in, const int* in_sizes, int n_in,
                              void* d_out, int out_size) {
    const float* feats = (const float*)d_in[0];
    const int*   idx   = (const int*)d_in[1];
    const float* W     = (const float*)d_in[2];
    const float* bvec  = (const float*)d_in[3];
    const float* gamma = (const float*)d_in[4];
    const float* beta  = (const float*)d_in[5];
    float* out = (float*)d_out;

    int M = in_sizes[0] / CC;   // 300000

    size_t smem_mma = (size_t)4 * 128 * SP * sizeof(__nv_bfloat16);   // 139264 B
    cudaFuncSetAttribute(k_gemm_all, cudaFuncAttributeMaxDynamicSharedMemorySize,
                         (int)smem_mma);

    int grid_slots = (NSC * NSLOTS + 255) / 256;
    int grid_pts   = (M + 255) / 256;
    int grid_8     = (M * 8 + 255) / 256;      // 9375 (single pass, all scales)
    int grid_warp  = (M * 32 + 255) / 256;     // 37500
    int grid_gemm  = (M + TM - 1) / TM;        // 2344

    dim3 ggemm(grid_gemm, NSC);
    dim3 gassign(NSLOTS / 256, NSC);
    dim3 gzero(512, NSC);

    k_clear_prep<<<grid_slots, 256>>>(W);
    k_build_all<<<grid_pts, 256>>>(idx, M);
    k_assign<<<gassign, 256>>>();
    k_flagaccum_all<<<grid_8, 256>>>(feats, M);
    k_gemm_all<<<ggemm, 256, smem_mma>>>(feats, bvec, out);
    k_zero_all<<<gzero, 256>>>();
    k_finalize_all<<<1, 512>>>(bvec, gamma, beta, M);
    k_norm_all<<<grid_warp, 256>>>(out, M);
}

// round 16
// speedup vs baseline: 1.1722x; 1.0113x over previous
#include <cuda_runtime.h>
#include <cuda_bf16.h>
#include <cstdint>
#include <cstddef>

// ---------------- problem constants ----------------
#define MAXPTS 300000
#define CC 128            // channels
#define NSC 4             // number of scales
#define COORDN 512u
#define NSLOTS (1u<<19)   // hash slots per scale
#define SLOT_MASK (NSLOTS-1u)
#define EMPTY_KEY 0xFFFFFFFFu
#define INV_DID 0xFFFFFFFFu
#define MAXB 150016       // worst-case non-singleton buckets per scale (M/2)
#define EPSV 1e-5f
#define SLOPEV 0.01f

#define TM 128            // GEMM rows per tile
#define SP 136            // smem row stride in bf16 (272B -> conflict-free)
#define NGB 148           // persistent GEMM blocks (1/SM)

// ---------------- device scratch (zero-init .bss) ----------------
__device__ unsigned g_keys[NSC * NSLOTS];
__device__ int      g_counts[NSC * NSLOTS];
__device__ unsigned g_dense[NSC * NSLOTS];               // slot -> dense bucket id (or INV)
__device__ int      g_ccount[NSC * MAXB];                // dense id -> count
__device__ float    g_csums[(size_t)NSC * MAXB * CC];    // compact sums (~54MB live; L2!)
__device__ unsigned g_slotflag[NSC * MAXPTS];            // did | singleton<<31
__device__ int      g_list[NSC * MAXPTS];
__device__ int      g_nnz[NSC];
__device__ int      g_nbuckets[NSC];
__device__ float    g_chanSum[NSC * CC];
__device__ float    g_chanSq[NSC * CC];
__device__ float    g_A[NSC * CC];
__device__ float    g_Bc[NSC * CC];
__device__ float    g_sv[NSC * CC];
__device__ __nv_bfloat16 g_WtHi[NSC * CC * CC];          // Wt[n][k] = bf16_hi(W[k][n])
__device__ __nv_bfloat16 g_WtLo[NSC * CC * CC];

__device__ __forceinline__ unsigned hash32(unsigned x) {
    x ^= x >> 16; x *= 0x7feb352dU;
    x ^= x >> 15; x *= 0x846ca68bU;
    x ^= x >> 16;
    return x;
}

__device__ __forceinline__ void mma_bf16(float& d0, float& d1, float& d2, float& d3,
                                         uint32_t a0, uint32_t a1, uint32_t a2, uint32_t a3,
                                         uint32_t b0, uint32_t b1) {
    asm volatile(
        "mma.sync.aligned.m16n8k16.row.col.f32.bf16.bf16.f32 "
        "{%0,%1,%2,%3}, {%4,%5,%6,%7}, {%8,%9}, {%0,%1,%2,%3};\n"
        : "+f"(d0), "+f"(d1), "+f"(d2), "+f"(d3)
        : "r"(a0), "r"(a1), "r"(a2), "r"(a3), "r"(b0), "r"(b1));
}

__device__ __forceinline__ void ldsm_x4(uint32_t& r0, uint32_t& r1, uint32_t& r2,
                                        uint32_t& r3, uint32_t addr) {
    asm volatile("ldmatrix.sync.aligned.m8n8.x4.shared.b16 {%0,%1,%2,%3}, [%4];"
                 : "=r"(r0), "=r"(r1), "=r"(r2), "=r"(r3) : "r"(addr));
}

__device__ __forceinline__ void red_v4(float* dst, float4 v) {
    asm volatile("red.global.add.v4.f32 [%0], {%1,%2,%3,%4};"
                 :: "l"(dst), "f"(v.x), "f"(v.y), "f"(v.z), "f"(v.w) : "memory");
}

// ---------------- kernels ----------------

// fused clear + W split-prep (independent index ranges)
__global__ void k_clear_prep(const float* __restrict__ W) {
    unsigned i = blockIdx.x * blockDim.x + threadIdx.x;
    if (i < NSC * NSLOTS) { g_keys[i] = EMPTY_KEY; g_counts[i] = 0; }
    if (i < NSC) { g_nnz[i] = 0; g_nbuckets[i] = 0; }
    if (i < NSC * CC * CC) {
        int s = i >> 14, rem = i & 16383, n = rem >> 7, k = rem & 127;
        float v = W[(size_t)s * CC * CC + k * CC + n];
        __nv_bfloat16 hi = __float2bfloat16_rn(v);
        __nv_bfloat16 lo = __float2bfloat16_rn(v - __bfloat162float(hi));
        g_WtHi[i] = hi;
        g_WtLo[i] = lo;
    }
}

// one thread per point; probes all 4 scale tables (idx loaded once, 4-way ILP)
__global__ void k_build_all(const int* __restrict__ idx, int M) {
    int p = blockIdx.x * blockDim.x + threadIdx.x;
    if (p >= M) return;
    int4 q = *(const int4*)(idx + p * 4);
    unsigned b = (unsigned)q.x;
    #pragma unroll
    for (int s = 0; s < NSC; s++) {
        int shift = s + 1;                       // scales 2,4,8,16
        unsigned cx = (unsigned)q.y >> shift;
        unsigned cy = (unsigned)q.z >> shift;
        unsigned cz = (unsigned)q.w >> shift;
        unsigned key = ((b * COORDN + cx) * COORDN + cy) * COORDN + cz;
        unsigned slot = hash32(key) & SLOT_MASK;
        unsigned* keys = g_keys + s * NSLOTS;
        while (true) {
            unsigned prev = atomicCAS(&keys[slot], EMPTY_KEY, key);
            if (prev == EMPTY_KEY || prev == key) break;
            slot = (slot + 1u) & SLOT_MASK;
        }
        g_slotflag[s * MAXPTS + p] = slot;
        atomicAdd(&g_counts[s * NSLOTS + slot], 1);
    }
}

// dense-id assignment: one thread per slot, block-aggregated counter.
__global__ void k_assign() {
    __shared__ int s_cnt, s_base;
    int s = blockIdx.y;
    int tid = threadIdx.x;
    unsigned i = blockIdx.x * blockDim.x + tid;
    if (tid == 0) s_cnt = 0;
    __syncthreads();
    int c = g_counts[s * NSLOTS + i];
    int pos = -1;
    if (c > 1) pos = atomicAdd(&s_cnt, 1);
    __syncthreads();
    if (tid == 0 && s_cnt > 0) s_base = atomicAdd(&g_nbuckets[s], s_cnt);
    __syncthreads();
    if (c > 1) {
        unsigned did = (unsigned)(s_base + pos);
        g_dense[s * NSLOTS + i] = did;
        g_ccount[s * MAXB + did] = c;
    } else {
        g_dense[s * NSLOTS + i] = INV_DID;
    }
}

// fused flag + accumulate, ONE pass over points (all scales inside):
// 8 threads/point; feats loaded once; 4-way MLP on the slot/dense gathers.
__global__ void k_flagaccum_all(const float* __restrict__ feats, int M) {
    __shared__ int s_cnt[NSC], s_base[NSC];
    __shared__ int s_pts[NSC][32];               // 32 points per 256-thread block
    int tid = threadIdx.x;
    if (tid < NSC) s_cnt[tid] = 0;
    __syncthreads();

    int g = blockIdx.x * blockDim.x + tid;
    int p = g >> 3;
    int li = g & 7;
    if (p < M) {
        unsigned slot[NSC];
        #pragma unroll
        for (int s = 0; s < NSC; s++) slot[s] = g_slotflag[s * MAXPTS + p];
        unsigned did[NSC];
        #pragma unroll
        for (int s = 0; s < NSC; s++) did[s] = g_dense[s * NSLOTS + slot[s]];

        bool any = false;
        #pragma unroll
        for (int s = 0; s < NSC; s++) {
            if (did[s] != INV_DID) {
                any = true;
                if (li == 0) {
                    int pos = atomicAdd(&s_cnt[s], 1);
                    s_pts[s][pos] = p;
                    g_slotflag[s * MAXPTS + p] = did[s];
                }
            } else if (li == 0) {
                g_slotflag[s * MAXPTS + p] = slot[s] | 0x80000000u;
            }
        }
        if (any) {
            const float4* src = (const float4*)(feats + (size_t)p * CC + li * 16);
            float4 v0 = src[0], v1 = src[1], v2 = src[2], v3 = src[3];
            #pragma unroll
            for (int s = 0; s < NSC; s++) {
                if (did[s] != INV_DID) {
                    float* dst = g_csums + ((size_t)s * MAXB + did[s]) * CC + li * 16;
                    red_v4(dst + 0,  v0);
                    red_v4(dst + 4,  v1);
                    red_v4(dst + 8,  v2);
                    red_v4(dst + 12, v3);
                }
            }
        }
    }
    __syncthreads();
    if (tid < NSC && s_cnt[tid] > 0)
        s_base[tid] = atomicAdd(&g_nnz[tid], s_cnt[tid]);
    __syncthreads();
    if (tid < NSC * 32) {
        int s = tid >> 5, j = tid & 31;
        if (j < s_cnt[s]) g_list[s * MAXPTS + s_base[s] + j] = s_pts[s][j];
    }
}

// re-zero the used compact csums region: SEQUENTIAL, coalesced
__global__ void k_zero_all() {
    int s = blockIdx.y;
    int n4 = g_nbuckets[s] * (CC / 4);
    float4* base = (float4*)(g_csums + (size_t)s * MAXB * CC);
    float4 z = make_float4(0.f, 0.f, 0.f, 0.f);
    for (int i = blockIdx.x * blockDim.x + threadIdx.x; i < n4;
         i += gridDim.x * blockDim.x)
        base[i] = z;
}

// ---- persistent HMMA bf16 split GEMM ----
// 148 CTAs; each handles a contiguous chunk of the global tile list.
// B smem-resident per scale-run; A double-buffered; next tile's FEATS
// (the DRAM-latency term) register-prefetched under the MMA; csums (L2-resident)
// read inline at convert time.
__global__ __launch_bounds__(256, 1)
void k_gemm_all(const float* __restrict__ feats, const float* __restrict__ bvec,
                float* __restrict__ out) {
    int cum[NSC + 1];
    cum[0] = 0;
    #pragma unroll
    for (int s = 0; s < NSC; s++) cum[s + 1] = cum[s] + (g_nnz[s] + TM - 1) / TM;
    int T = cum[NSC];
    int G = gridDim.x, b = blockIdx.x;
    int lo = (int)(((long long)b * T) / G);
    int hi = (int)(((long long)(b + 1) * T) / G);
    if (lo >= hi) return;

    extern __shared__ __nv_bfloat16 sm[];
    __nv_bfloat16* BHI = sm + 4 * 128 * SP;      // A buffers occupy sm[0 .. 4*128*SP)
    __nv_bfloat16* BLO = sm + 5 * 128 * SP;
    __shared__ float bsum[CC], bsq[CC], bsh[CC];

    int tid = threadIdx.x;
    int wid = tid >> 5;
    int lane = tid & 31;
    int rr = tid >> 1, kh = (tid & 1) << 6;

    uint32_t sBHI = (uint32_t)__cvta_generic_to_shared(BHI);
    uint32_t sBLO = (uint32_t)__cvta_generic_to_shared(BLO);
    uint32_t aoff_lane = (uint32_t)((wid * 16 + (lane & 7) + ((lane >> 3) & 1) * 8) * SP
                                    + (lane >> 4) * 8) * 2u;
    uint32_t boff = (uint32_t)(((lane & 7) + ((lane >> 4) & 1) * 8) * SP
                               + ((lane >> 3) & 1) * 8) * 2u;

    int cur_s = -1;

    // cross-tile prefetch state: FULL 64-channel half-row of feats (16 float4)
    float4 pf[16];
    unsigned pdid = 0;
    float pinv = 0.f;
    bool pvalid = false;

    int ns, nbase;   // decoded next tile
    {
        int t0 = lo;
        ns = 0;
        #pragma unroll
        for (int k = 1; k < NSC; k++) if (t0 >= cum[k]) ns = k;
        nbase = (t0 - cum[ns]) * TM;
    }
    // preload tile lo
    {
        int li = nbase + rr;
        pvalid = li < g_nnz[ns];
        int p = pvalid ? g_list[ns * MAXPTS + li] : 0;
        pdid = pvalid ? g_slotflag[ns * MAXPTS + p] : 0u;
        pinv = pvalid ? 1.0f / (float)g_ccount[ns * MAXB + pdid] : 0.f;
        const float4* fp = (const float4*)(feats + (size_t)p * CC + kh);
        #pragma unroll
        for (int j = 0; j < 16; j++)
            pf[j] = pvalid ? fp[j] : make_float4(0.f, 0.f, 0.f, 0.f);
    }

    for (int t = lo; t < hi; t++) {
        int s = ns, base = nbase;

        if (s != cur_s) {
            // stage B for scale s (previous MMA reads finished: epilogue sync)
            const uint4* whi = (const uint4*)(g_WtHi + (size_t)s * CC * CC + rr * CC + kh);
            const uint4* wlo = (const uint4*)(g_WtLo + (size_t)s * CC * CC + rr * CC + kh);
            uint4* dhB = (uint4*)(BHI + rr * SP + kh);
            uint4* dlB = (uint4*)(BLO + rr * SP + kh);
            #pragma unroll
            for (int kk = 0; kk < 8; kk++) { dhB[kk] = whi[kk]; dlB[kk] = wlo[kk]; }
            if (tid < CC) bsh[tid] = bvec[s * CC + tid];
            cur_s = s;
        }
        if (tid < CC) { bsum[tid] = 0.f; bsq[tid] = 0.f; }

        int buf = t & 1;
        __nv_bfloat16* AHI = sm + (2 * buf) * 128 * SP;
        __nv_bfloat16* ALO = sm + (2 * buf + 1) * 128 * SP;

        // convert: prefetched feats + inline csums (L2) -> A smem (full 64ch half)
        {
            const float4* sp = (const float4*)(g_csums + ((size_t)s * MAXB + pdid) * CC + kh);
            uint32_t* dh = (uint32_t*)(AHI + rr * SP + kh);
            uint32_t* dl = (uint32_t*)(ALO + rr * SP + kh);
            #pragma unroll
            for (int j = 0; j < 16; j++) {
                float4 f = pf[j];
                float4 sv = pvalid ? sp[j] : make_float4(0.f, 0.f, 0.f, 0.f);
                float o0 = (f.x - sv.x * pinv) * f.x;
                float o1 = (f.y - sv.y * pinv) * f.y;
                float o2 = (f.z - sv.z * pinv) * f.z;
                float o3 = (f.w - sv.w * pinv) * f.w;
                __nv_bfloat162 h0 = __floats2bfloat162_rn(o0, o1);
                __nv_bfloat162 h1 = __floats2bfloat162_rn(o2, o3);
                __nv_bfloat162 l0 = __floats2bfloat162_rn(o0 - __bfloat162float(h0.x),
                                                          o1 - __bfloat162float(h0.y));
                __nv_bfloat162 l1 = __floats2bfloat162_rn(o2 - __bfloat162float(h1.x),
                                                          o3 - __bfloat162float(h1.y));
                uint2 hv, lv;
                hv.x = *(uint32_t*)&h0; hv.y = *(uint32_t*)&h1;
                lv.x = *(uint32_t*)&l0; lv.y = *(uint32_t*)&l1;
                *(uint2*)(dh + j * 2) = hv;
                *(uint2*)(dl + j * 2) = lv;
            }
        }
        __syncthreads();

        int nnz_cur = g_nnz[s];

        // prefetch next tile's feats during MMA
        if (t + 1 < hi) {
            int t1 = t + 1;
            ns = 0;
            #pragma unroll
            for (int k = 1; k < NSC; k++) if (t1 >= cum[k]) ns = k;
            nbase = (t1 - cum[ns]) * TM;
            int li = nbase + rr;
            pvalid = li < g_nnz[ns];
            int p = pvalid ? g_list[ns * MAXPTS + li] : 0;
            pdid = pvalid ? g_slotflag[ns * MAXPTS + p] : 0u;
            pinv = pvalid ? 1.0f / (float)g_ccount[ns * MAXB + pdid] : 0.f;
            const float4* fp = (const float4*)(feats + (size_t)p * CC + kh);
            #pragma unroll
            for (int j = 0; j < 16; j++)
                pf[j] = pvalid ? fp[j] : make_float4(0.f, 0.f, 0.f, 0.f);
        }

        // ---- MMA mainloop ----
        float acc[16][4];
        #pragma unroll
        for (int n = 0; n < 16; n++)
            #pragma unroll
            for (int j = 0; j < 4; j++) acc[n][j] = 0.f;

        uint32_t sAHI = (uint32_t)__cvta_generic_to_shared(AHI);
        uint32_t sALO = (uint32_t)__cvta_generic_to_shared(ALO);

        #pragma unroll
        for (int kt = 0; kt < 8; kt++) {
            uint32_t k0b = (uint32_t)kt * 32u;
            uint32_t ah0, ah1, ah2, ah3, al0, al1, al2, al3;
            ldsm_x4(ah0, ah1, ah2, ah3, sAHI + aoff_lane + k0b);
            ldsm_x4(al0, al1, al2, al3, sALO + aoff_lane + k0b);
            #pragma unroll
            for (int ntp = 0; ntp < 8; ntp++) {
                uint32_t bo = boff + (uint32_t)ntp * (16u * SP * 2u) + k0b;
                uint32_t bh0, bh1, bh2, bh3, bl0, bl1, bl2, bl3;
                ldsm_x4(bh0, bh1, bh2, bh3, sBHI + bo);
                ldsm_x4(bl0, bl1, bl2, bl3, sBLO + bo);
                int n0 = 2 * ntp, n1 = 2 * ntp + 1;
                mma_bf16(acc[n0][0], acc[n0][1], acc[n0][2], acc[n0][3],
                         ah0, ah1, ah2, ah3, bh0, bh1);
                mma_bf16(acc[n0][0], acc[n0][1], acc[n0][2], acc[n0][3],
                         ah0, ah1, ah2, ah3, bl0, bl1);
                mma_bf16(acc[n0][0], acc[n0][1], acc[n0][2], acc[n0][3],
                         al0, al1, al2, al3, bh0, bh1);
                mma_bf16(acc[n1][0], acc[n1][1], acc[n1][2], acc[n1][3],
                         ah0, ah1, ah2, ah3, bh2, bh3);
                mma_bf16(acc[n1][0], acc[n1][1], acc[n1][2], acc[n1][3],
                         ah0, ah1, ah2, ah3, bl2, bl3);
                mma_bf16(acc[n1][0], acc[n1][1], acc[n1][2], acc[n1][3],
                         al0, al1, al2, al3, bh2, bh3);
            }
        }

        // ---- epilogue ----
        int r0 = base + wid * 16 + (lane >> 2);
        int r1 = r0 + 8;
        bool v0 = r0 < nnz_cur, v1 = r1 < nnz_cur;
        int p0 = v0 ? g_list[s * MAXPTS + r0] : 0;
        int p1 = v1 ? g_list[s * MAXPTS + r1] : 0;
        float* o0 = out + ((size_t)p0 * NSC + s) * CC;
        float* o1 = out + ((size_t)p1 * NSC + s) * CC;

        #pragma unroll
        for (int n = 0; n < 16; n++) {
            int c0 = n * 8 + ((lane & 3) << 1);
            float bx = bsh[c0], by = bsh[c0 + 1];
            float h0x = acc[n][0] + bx, h0y = acc[n][1] + by;
            float h1x = acc[n][2] + bx, h1y = acc[n][3] + by;
            if (v0) __stcs((float2*)(o0 + c0), make_float2(h0x, h0y));
            if (v1) __stcs((float2*)(o1 + c0), make_float2(h1x, h1y));
            float sx = (v0 ? h0x : 0.f) + (v1 ? h1x : 0.f);
            float sy = (v0 ? h0y : 0.f) + (v1 ? h1y : 0.f);
            float qx = (v0 ? h0x * h0x : 0.f) + (v1 ? h1x * h1x : 0.f);
            float qy = (v0 ? h0y * h0y : 0.f) + (v1 ? h1y * h1y : 0.f);
            #pragma unroll
            for (int o = 4; o < 32; o <<= 1) {
                sx += __shfl_xor_sync(0xFFFFFFFFu, sx, o);
                sy += __shfl_xor_sync(0xFFFFFFFFu, sy, o);
                qx += __shfl_xor_sync(0xFFFFFFFFu, qx, o);
                qy += __shfl_xor_sync(0xFFFFFFFFu, qy, o);
            }
            if (lane < 4) {
                atomicAdd(&bsum[c0],     sx);
                atomicAdd(&bsum[c0 + 1], sy);
                atomicAdd(&bsq[c0],      qx);
                atomicAdd(&bsq[c0 + 1],  qy);
            }
        }
        __syncthreads();   // all MMA/epilogue done: safe to flush, restage B, reuse A buf
        if (tid < CC) {
            atomicAdd(&g_chanSum[s * CC + tid], bsum[tid]);
            atomicAdd(&g_chanSq[s * CC + tid],  bsq[tid]);
        }
    }
}

// all scales in one block: tid = s*128 + c
__global__ void k_finalize_all(const float* __restrict__ bvec, const float* __restrict__ gamma,
                               const float* __restrict__ beta, int M) {
    int t = threadIdx.x;           // 512 threads
    int s = t >> 7, c = t & 127;
    int i = s * CC + c;
    float bc = bvec[i];
    float rem = (float)(M - g_nnz[s]);
    float sum = g_chanSum[i] + rem * bc;
    float sq  = g_chanSq[i]  + rem * bc * bc;
    float mu  = sum / (float)M;
    float var = sq / (float)M - mu * mu;
    float A = rsqrtf(var + EPSV) * gamma[i];
    float B = beta[i] - mu * A;
    g_A[i]  = A;
    g_Bc[i] = B;
    float tv = bc * A + B;
    g_sv[i] = tv > 0.f ? tv : SLOPEV * tv;
    g_chanSum[i] = 0.f;
    g_chanSq[i]  = 0.f;
}

// fused normalize over all 4 scales: one warp per point, 2KB contiguous row
__global__ __launch_bounds__(256)
void k_norm_all(float* __restrict__ out, int M) {
    __shared__ float sA[NSC * CC], sB[NSC * CC], sSV[NSC * CC];
    int tid = threadIdx.x;
    for (int i = tid; i < NSC * CC; i += 256) {
        sA[i] = g_A[i]; sB[i] = g_Bc[i]; sSV[i] = g_sv[i];
    }
    __syncthreads();

    int g = blockIdx.x * blockDim.x + threadIdx.x;
    int p = g >> 5;
    if (p >= M) return;
    int lane = g & 31;
    int c4 = lane << 2;

    unsigned myf = (lane < NSC) ? g_slotflag[lane * MAXPTS + p] : 0u;
    float* op = out + (size_t)p * NSC * CC;

    #pragma unroll
    for (int s = 0; s < NSC; s++) {
        unsigned sing = __shfl_sync(0xFFFFFFFFu, myf, s) & 0x80000000u;
        float* q = op + s * CC + c4;
        float4 v;
        if (sing) {
            v = *(const float4*)(sSV + s * CC + c4);
        } else {
            float4 h = __ldcs((const float4*)q);
            const float* Ap = sA + s * CC + c4;
            const float* Bp = sB + s * CC + c4;
            v.x = h.x * Ap[0] + Bp[0];
            v.y = h.y * Ap[1] + Bp[1];
            v.z = h.z * Ap[2] + Bp[2];
            v.w = h.w * Ap[3] + Bp[3];
            v.x = v.x > 0.f ? v.x : SLOPEV * v.x;
            v.y = v.y > 0.f ? v.y : SLOPEV * v.y;
            v.z = v.z > 0.f ? v.z : SLOPEV * v.z;
            v.w = v.w > 0.f ? v.w : SLOPEV * v.w;
        }
        __stcs((float4*)q, v);
    }
}

// ---------------- launcher ----------------
extern "C" void kernel_launch(void* const* d_in, const int* in_sizes, int n_in,
                              void* d_out, int out_size) {
    const float* feats = (const float*)d_in[0];
    const int*   idx   = (const int*)d_in[1];
    const float* W     = (const float*)d_in[2];
    const float* bvec  = (const float*)d_in[3];
    const float* gamma = (const float*)d_in[4];
    const float* beta  = (const float*)d_in[5];
    float* out = (float*)d_out;

    int M = in_sizes[0] / CC;   // 300000

    size_t smem_mma = (size_t)6 * 128 * SP * sizeof(__nv_bfloat16);   // 208896 B
    cudaFuncSetAttribute(k_gemm_all, cudaFuncAttributeMaxDynamicSharedMemorySize,
                         (int)smem_mma);

    int grid_slots = (NSC * NSLOTS + 255) / 256;
    int grid_pts   = (M + 255) / 256;
    int grid_8     = (M * 8 + 255) / 256;      // 9375 (single pass, all scales)
    int grid_warp  = (M * 32 + 255) / 256;     // 37500

    dim3 gassign(NSLOTS / 256, NSC);
    dim3 gzero(512, NSC);

    k_clear_prep<<<grid_slots, 256>>>(W);
    k_build_all<<<grid_pts, 256>>>(idx, M);
    k_assign<<<gassign, 256>>>();
    k_flagaccum_all<<<grid_8, 256>>>(feats, M);
    k_gemm_all<<<NGB, 256, smem_mma>>>(feats, bvec, out);
    k_zero_all<<<gzero, 256>>>();
    k_finalize_all<<<1, 512>>>(bvec, gamma, beta, M);
    k_norm_all<<<grid_warp, 256>>>(out, M);
}

// round 17
// speedup vs baseline: 1.1809x; 1.0074x over previous
#include <cuda_runtime.h>
#include <cuda_bf16.h>
#include <cstdint>
#include <cstddef>

// ---------------- problem constants ----------------
#define MAXPTS 300000
#define CC 128            // channels
#define NSC 4             // number of scales
#define COORDN 512u
#define NSLOTS (1u<<19)   // hash slots per scale
#define SLOT_MASK (NSLOTS-1u)
// empty slot == 0 (matches .bss zero-init and cheap tail-clear); stored key = key+1
#define INV_DID 0xFFFFFFFFu
#define MAXB 150016       // worst-case non-singleton buckets per scale (M/2)
#define EPSV 1e-5f
#define SLOPEV 0.01f

#define TM 128            // GEMM rows per tile
#define SP 136            // smem row stride in bf16 (272B -> conflict-free)
#define NGB 148           // persistent GEMM blocks (1/SM)

// ---------------- device scratch (zero-init .bss) ----------------
__device__ unsigned g_keys[NSC * NSLOTS];                // 0 = empty
__device__ int      g_counts[NSC * NSLOTS];
__device__ unsigned g_dense[NSC * NSLOTS];               // slot -> dense bucket id (or INV)
__device__ int      g_ccount[NSC * MAXB];                // dense id -> count
__device__ float    g_csums[(size_t)NSC * MAXB * CC];    // compact sums (~54MB live; L2!)
__device__ unsigned g_slotflag[NSC * MAXPTS];            // did | singleton<<31
__device__ int      g_list[NSC * MAXPTS];
__device__ int      g_nnz[NSC];
__device__ int      g_nbuckets[NSC];
__device__ float    g_chanSum[NSC * CC];
__device__ float    g_chanSq[NSC * CC];
__device__ float    g_A[NSC * CC];
__device__ float    g_Bc[NSC * CC];
__device__ float    g_sv[NSC * CC];
__device__ __nv_bfloat16 g_WtHi[NSC * CC * CC];          // Wt[n][k] = bf16_hi(W[k][n])
__device__ __nv_bfloat16 g_WtLo[NSC * CC * CC];

__device__ __forceinline__ unsigned hash32(unsigned x) {
    x ^= x >> 16; x *= 0x7feb352dU;
    x ^= x >> 15; x *= 0x846ca68bU;
    x ^= x >> 16;
    return x;
}

__device__ __forceinline__ void mma_bf16(float& d0, float& d1, float& d2, float& d3,
                                         uint32_t a0, uint32_t a1, uint32_t a2, uint32_t a3,
                                         uint32_t b0, uint32_t b1) {
    asm volatile(
        "mma.sync.aligned.m16n8k16.row.col.f32.bf16.bf16.f32 "
        "{%0,%1,%2,%3}, {%4,%5,%6,%7}, {%8,%9}, {%0,%1,%2,%3};\n"
        : "+f"(d0), "+f"(d1), "+f"(d2), "+f"(d3)
        : "r"(a0), "r"(a1), "r"(a2), "r"(a3), "r"(b0), "r"(b1));
}

__device__ __forceinline__ void ldsm_x4(uint32_t& r0, uint32_t& r1, uint32_t& r2,
                                        uint32_t& r3, uint32_t addr) {
    asm volatile("ldmatrix.sync.aligned.m8n8.x4.shared.b16 {%0,%1,%2,%3}, [%4];"
                 : "=r"(r0), "=r"(r1), "=r"(r2), "=r"(r3) : "r"(addr));
}

__device__ __forceinline__ void red_v4(float* dst, float4 v) {
    asm volatile("red.global.add.v4.f32 [%0], {%1,%2,%3,%4};"
                 :: "l"(dst), "f"(v.x), "f"(v.y), "f"(v.z), "f"(v.w) : "memory");
}

// ---------------- kernels ----------------

// head prep: W split + per-call counter reset (keys/counts cleared in k_norm_all tail)
__global__ void k_prep(const float* __restrict__ W) {
    int i = blockIdx.x * blockDim.x + threadIdx.x;
    if (i < NSC) { g_nnz[i] = 0; g_nbuckets[i] = 0; }
    if (i < NSC * CC * CC) {
        int s = i >> 14, rem = i & 16383, n = rem >> 7, k = rem & 127;
        float v = W[(size_t)s * CC * CC + k * CC + n];
        __nv_bfloat16 hi = __float2bfloat16_rn(v);
        __nv_bfloat16 lo = __float2bfloat16_rn(v - __bfloat162float(hi));
        g_WtHi[i] = hi;
        g_WtLo[i] = lo;
    }
}

// one thread per point; probes all 4 scale tables (idx loaded once, 4-way ILP)
__global__ void k_build_all(const int* __restrict__ idx, int M) {
    int p = blockIdx.x * blockDim.x + threadIdx.x;
    if (p >= M) return;
    int4 q = *(const int4*)(idx + p * 4);
    unsigned b = (unsigned)q.x;
    #pragma unroll
    for (int s = 0; s < NSC; s++) {
        int shift = s + 1;                       // scales 2,4,8,16
        unsigned cx = (unsigned)q.y >> shift;
        unsigned cy = (unsigned)q.z >> shift;
        unsigned cz = (unsigned)q.w >> shift;
        unsigned key = ((b * COORDN + cx) * COORDN + cy) * COORDN + cz + 1u;  // != 0
        unsigned slot = hash32(key) & SLOT_MASK;
        unsigned* keys = g_keys + s * NSLOTS;
        while (true) {
            unsigned prev = atomicCAS(&keys[slot], 0u, key);
            if (prev == 0u || prev == key) break;
            slot = (slot + 1u) & SLOT_MASK;
        }
        g_slotflag[s * MAXPTS + p] = slot;
        atomicAdd(&g_counts[s * NSLOTS + slot], 1);
    }
}

// dense-id assignment: one thread per slot, block-aggregated counter.
__global__ void k_assign() {
    __shared__ int s_cnt, s_base;
    int s = blockIdx.y;
    int tid = threadIdx.x;
    unsigned i = blockIdx.x * blockDim.x + tid;
    if (tid == 0) s_cnt = 0;
    __syncthreads();
    int c = g_counts[s * NSLOTS + i];
    int pos = -1;
    if (c > 1) pos = atomicAdd(&s_cnt, 1);
    __syncthreads();
    if (tid == 0 && s_cnt > 0) s_base = atomicAdd(&g_nbuckets[s], s_cnt);
    __syncthreads();
    if (c > 1) {
        unsigned did = (unsigned)(s_base + pos);
        g_dense[s * NSLOTS + i] = did;
        g_ccount[s * MAXB + did] = c;
    } else {
        g_dense[s * NSLOTS + i] = INV_DID;
    }
}

// fused flag + accumulate, ONE pass over points, 4 threads/point (32ch each).
__global__ void k_flagaccum_all(const float* __restrict__ feats, int M) {
    __shared__ int s_cnt[NSC], s_base[NSC];
    __shared__ int s_pts[NSC][64];               // 64 points per 256-thread block
    int tid = threadIdx.x;
    if (tid < NSC) s_cnt[tid] = 0;
    __syncthreads();

    int g = blockIdx.x * blockDim.x + tid;
    int p = g >> 2;
    int li = g & 3;
    if (p < M) {
        unsigned slot[NSC];
        #pragma unroll
        for (int s = 0; s < NSC; s++) slot[s] = g_slotflag[s * MAXPTS + p];
        unsigned did[NSC];
        #pragma unroll
        for (int s = 0; s < NSC; s++) did[s] = g_dense[s * NSLOTS + slot[s]];

        bool any = false;
        #pragma unroll
        for (int s = 0; s < NSC; s++) {
            if (did[s] != INV_DID) {
                any = true;
                if (li == 0) {
                    int pos = atomicAdd(&s_cnt[s], 1);
                    s_pts[s][pos] = p;
                    g_slotflag[s * MAXPTS + p] = did[s];
                }
            } else if (li == 0) {
                g_slotflag[s * MAXPTS + p] = slot[s] | 0x80000000u;
            }
        }
        if (any) {
            const float4* src = (const float4*)(feats + (size_t)p * CC + li * 32);
            float4 v[8];
            #pragma unroll
            for (int j = 0; j < 8; j++) v[j] = src[j];
            #pragma unroll
            for (int s = 0; s < NSC; s++) {
                if (did[s] != INV_DID) {
                    float* dst = g_csums + ((size_t)s * MAXB + did[s]) * CC + li * 32;
                    #pragma unroll
                    for (int j = 0; j < 8; j++) red_v4(dst + j * 4, v[j]);
                }
            }
        }
    }
    __syncthreads();
    if (tid < NSC && s_cnt[tid] > 0)
        s_base[tid] = atomicAdd(&g_nnz[tid], s_cnt[tid]);
    __syncthreads();
    {
        int s = tid >> 6, j = tid & 63;          // 256 threads = 4 x 64
        if (j < s_cnt[s]) g_list[s * MAXPTS + s_base[s] + j] = s_pts[s][j];
    }
}

// ---- persistent HMMA bf16 split GEMM (unchanged from R16) ----
__global__ __launch_bounds__(256, 1)
void k_gemm_all(const float* __restrict__ feats, const float* __restrict__ bvec,
                float* __restrict__ out) {
    int cum[NSC + 1];
    cum[0] = 0;
    #pragma unroll
    for (int s = 0; s < NSC; s++) cum[s + 1] = cum[s] + (g_nnz[s] + TM - 1) / TM;
    int T = cum[NSC];
    int G = gridDim.x, b = blockIdx.x;
    int lo = (int)(((long long)b * T) / G);
    int hi = (int)(((long long)(b + 1) * T) / G);
    if (lo >= hi) return;

    extern __shared__ __nv_bfloat16 sm[];
    __nv_bfloat16* BHI = sm + 4 * 128 * SP;
    __nv_bfloat16* BLO = sm + 5 * 128 * SP;
    __shared__ float bsum[CC], bsq[CC], bsh[CC];

    int tid = threadIdx.x;
    int wid = tid >> 5;
    int lane = tid & 31;
    int rr = tid >> 1, kh = (tid & 1) << 6;

    uint32_t sBHI = (uint32_t)__cvta_generic_to_shared(BHI);
    uint32_t sBLO = (uint32_t)__cvta_generic_to_shared(BLO);
    uint32_t aoff_lane = (uint32_t)((wid * 16 + (lane & 7) + ((lane >> 3) & 1) * 8) * SP
                                    + (lane >> 4) * 8) * 2u;
    uint32_t boff = (uint32_t)(((lane & 7) + ((lane >> 4) & 1) * 8) * SP
                               + ((lane >> 3) & 1) * 8) * 2u;

    int cur_s = -1;
    float4 pf[16];
    unsigned pdid = 0;
    float pinv = 0.f;
    bool pvalid = false;

    int ns, nbase;
    {
        int t0 = lo;
        ns = 0;
        #pragma unroll
        for (int k = 1; k < NSC; k++) if (t0 >= cum[k]) ns = k;
        nbase = (t0 - cum[ns]) * TM;
    }
    {
        int li = nbase + rr;
        pvalid = li < g_nnz[ns];
        int p = pvalid ? g_list[ns * MAXPTS + li] : 0;
        pdid = pvalid ? g_slotflag[ns * MAXPTS + p] : 0u;
        pinv = pvalid ? 1.0f / (float)g_ccount[ns * MAXB + pdid] : 0.f;
        const float4* fp = (const float4*)(feats + (size_t)p * CC + kh);
        #pragma unroll
        for (int j = 0; j < 16; j++)
            pf[j] = pvalid ? fp[j] : make_float4(0.f, 0.f, 0.f, 0.f);
    }

    for (int t = lo; t < hi; t++) {
        int s = ns, base = nbase;

        if (s != cur_s) {
            const uint4* whi = (const uint4*)(g_WtHi + (size_t)s * CC * CC + rr * CC + kh);
            const uint4* wlo = (const uint4*)(g_WtLo + (size_t)s * CC * CC + rr * CC + kh);
            uint4* dhB = (uint4*)(BHI + rr * SP + kh);
            uint4* dlB = (uint4*)(BLO + rr * SP + kh);
            #pragma unroll
            for (int kk = 0; kk < 8; kk++) { dhB[kk] = whi[kk]; dlB[kk] = wlo[kk]; }
            if (tid < CC) bsh[tid] = bvec[s * CC + tid];
            cur_s = s;
        }
        if (tid < CC) { bsum[tid] = 0.f; bsq[tid] = 0.f; }

        int buf = t & 1;
        __nv_bfloat16* AHI = sm + (2 * buf) * 128 * SP;
        __nv_bfloat16* ALO = sm + (2 * buf + 1) * 128 * SP;

        {
            const float4* sp = (const float4*)(g_csums + ((size_t)s * MAXB + pdid) * CC + kh);
            uint32_t* dh = (uint32_t*)(AHI + rr * SP + kh);
            uint32_t* dl = (uint32_t*)(ALO + rr * SP + kh);
            #pragma unroll
            for (int j = 0; j < 16; j++) {
                float4 f = pf[j];
                float4 sv = pvalid ? sp[j] : make_float4(0.f, 0.f, 0.f, 0.f);
                float o0 = (f.x - sv.x * pinv) * f.x;
                float o1 = (f.y - sv.y * pinv) * f.y;
                float o2 = (f.z - sv.z * pinv) * f.z;
                float o3 = (f.w - sv.w * pinv) * f.w;
                __nv_bfloat162 h0 = __floats2bfloat162_rn(o0, o1);
                __nv_bfloat162 h1 = __floats2bfloat162_rn(o2, o3);
                __nv_bfloat162 l0 = __floats2bfloat162_rn(o0 - __bfloat162float(h0.x),
                                                          o1 - __bfloat162float(h0.y));
                __nv_bfloat162 l1 = __floats2bfloat162_rn(o2 - __bfloat162float(h1.x),
                                                          o3 - __bfloat162float(h1.y));
                uint2 hv, lv;
                hv.x = *(uint32_t*)&h0; hv.y = *(uint32_t*)&h1;
                lv.x = *(uint32_t*)&l0; lv.y = *(uint32_t*)&l1;
                *(uint2*)(dh + j * 2) = hv;
                *(uint2*)(dl + j * 2) = lv;
            }
        }
        __syncthreads();

        int nnz_cur = g_nnz[s];

        if (t + 1 < hi) {
            int t1 = t + 1;
            ns = 0;
            #pragma unroll
            for (int k = 1; k < NSC; k++) if (t1 >= cum[k]) ns = k;
            nbase = (t1 - cum[ns]) * TM;
            int li = nbase + rr;
            pvalid = li < g_nnz[ns];
            int p = pvalid ? g_list[ns * MAXPTS + li] : 0;
            pdid = pvalid ? g_slotflag[ns * MAXPTS + p] : 0u;
            pinv = pvalid ? 1.0f / (float)g_ccount[ns * MAXB + pdid] : 0.f;
            const float4* fp = (const float4*)(feats + (size_t)p * CC + kh);
            #pragma unroll
            for (int j = 0; j < 16; j++)
                pf[j] = pvalid ? fp[j] : make_float4(0.f, 0.f, 0.f, 0.f);
        }

        float acc[16][4];
        #pragma unroll
        for (int n = 0; n < 16; n++)
            #pragma unroll
            for (int j = 0; j < 4; j++) acc[n][j] = 0.f;

        uint32_t sAHI = (uint32_t)__cvta_generic_to_shared(AHI);
        uint32_t sALO = (uint32_t)__cvta_generic_to_shared(ALO);

        #pragma unroll
        for (int kt = 0; kt < 8; kt++) {
            uint32_t k0b = (uint32_t)kt * 32u;
            uint32_t ah0, ah1, ah2, ah3, al0, al1, al2, al3;
            ldsm_x4(ah0, ah1, ah2, ah3, sAHI + aoff_lane + k0b);
            ldsm_x4(al0, al1, al2, al3, sALO + aoff_lane + k0b);
            #pragma unroll
            for (int ntp = 0; ntp < 8; ntp++) {
                uint32_t bo = boff + (uint32_t)ntp * (16u * SP * 2u) + k0b;
                uint32_t bh0, bh1, bh2, bh3, bl0, bl1, bl2, bl3;
                ldsm_x4(bh0, bh1, bh2, bh3, sBHI + bo);
                ldsm_x4(bl0, bl1, bl2, bl3, sBLO + bo);
                int n0 = 2 * ntp, n1 = 2 * ntp + 1;
                mma_bf16(acc[n0][0], acc[n0][1], acc[n0][2], acc[n0][3],
                         ah0, ah1, ah2, ah3, bh0, bh1);
                mma_bf16(acc[n0][0], acc[n0][1], acc[n0][2], acc[n0][3],
                         ah0, ah1, ah2, ah3, bl0, bl1);
                mma_bf16(acc[n0][0], acc[n0][1], acc[n0][2], acc[n0][3],
                         al0, al1, al2, al3, bh0, bh1);
                mma_bf16(acc[n1][0], acc[n1][1], acc[n1][2], acc[n1][3],
                         ah0, ah1, ah2, ah3, bh2, bh3);
                mma_bf16(acc[n1][0], acc[n1][1], acc[n1][2], acc[n1][3],
                         ah0, ah1, ah2, ah3, bl2, bl3);
                mma_bf16(acc[n1][0], acc[n1][1], acc[n1][2], acc[n1][3],
                         al0, al1, al2, al3, bh2, bh3);
            }
        }

        int r0 = base + wid * 16 + (lane >> 2);
        int r1 = r0 + 8;
        bool v0 = r0 < nnz_cur, v1 = r1 < nnz_cur;
        int p0 = v0 ? g_list[s * MAXPTS + r0] : 0;
        int p1 = v1 ? g_list[s * MAXPTS + r1] : 0;
        float* o0 = out + ((size_t)p0 * NSC + s) * CC;
        float* o1 = out + ((size_t)p1 * NSC + s) * CC;

        #pragma unroll
        for (int n = 0; n < 16; n++) {
            int c0 = n * 8 + ((lane & 3) << 1);
            float bx = bsh[c0], by = bsh[c0 + 1];
            float h0x = acc[n][0] + bx, h0y = acc[n][1] + by;
            float h1x = acc[n][2] + bx, h1y = acc[n][3] + by;
            if (v0) __stcs((float2*)(o0 + c0), make_float2(h0x, h0y));
            if (v1) __stcs((float2*)(o1 + c0), make_float2(h1x, h1y));
            float sx = (v0 ? h0x : 0.f) + (v1 ? h1x : 0.f);
            float sy = (v0 ? h0y : 0.f) + (v1 ? h1y : 0.f);
            float qx = (v0 ? h0x * h0x : 0.f) + (v1 ? h1x * h1x : 0.f);
            float qy = (v0 ? h0y * h0y : 0.f) + (v1 ? h1y * h1y : 0.f);
            #pragma unroll
            for (int o = 4; o < 32; o <<= 1) {
                sx += __shfl_xor_sync(0xFFFFFFFFu, sx, o);
                sy += __shfl_xor_sync(0xFFFFFFFFu, sy, o);
                qx += __shfl_xor_sync(0xFFFFFFFFu, qx, o);
                qy += __shfl_xor_sync(0xFFFFFFFFu, qy, o);
            }
            if (lane < 4) {
                atomicAdd(&bsum[c0],     sx);
                atomicAdd(&bsum[c0 + 1], sy);
                atomicAdd(&bsq[c0],      qx);
                atomicAdd(&bsq[c0 + 1],  qy);
            }
        }
        __syncthreads();
        if (tid < CC) {
            atomicAdd(&g_chanSum[s * CC + tid], bsum[tid]);
            atomicAdd(&g_chanSq[s * CC + tid],  bsq[tid]);
        }
    }
}

// all scales in one block: tid = s*128 + c
__global__ void k_finalize_all(const float* __restrict__ bvec, const float* __restrict__ gamma,
                               const float* __restrict__ beta, int M) {
    int t = threadIdx.x;           // 512 threads
    int s = t >> 7, c = t & 127;
    int i = s * CC + c;
    float bc = bvec[i];
    float rem = (float)(M - g_nnz[s]);
    float sum = g_chanSum[i] + rem * bc;
    float sq  = g_chanSq[i]  + rem * bc * bc;
    float mu  = sum / (float)M;
    float var = sq / (float)M - mu * mu;
    float A = rsqrtf(var + EPSV) * gamma[i];
    float B = beta[i] - mu * A;
    g_A[i]  = A;
    g_Bc[i] = B;
    float tv = bc * A + B;
    g_sv[i] = tv > 0.f ? tv : SLOPEV * tv;
    g_chanSum[i] = 0.f;
    g_chanSq[i]  = 0.f;
}

// fused normalize over all 4 scales + TAIL CLEANUP (keys/counts/csums zeroing)
__global__ __launch_bounds__(256)
void k_norm_all(float* __restrict__ out, int M) {
    __shared__ float sA[NSC * CC], sB[NSC * CC], sSV[NSC * CC];
    int tid = threadIdx.x;
    for (int i = tid; i < NSC * CC; i += 256) {
        sA[i] = g_A[i]; sB[i] = g_Bc[i]; sSV[i] = g_sv[i];
    }
    __syncthreads();

    int g = blockIdx.x * blockDim.x + threadIdx.x;
    int p = g >> 5;
    int lane = g & 31;
    int c4 = lane << 2;

    if (p < M) {
        unsigned myf = (lane < NSC) ? g_slotflag[lane * MAXPTS + p] : 0u;
        float* op = out + (size_t)p * NSC * CC;

        #pragma unroll
        for (int s = 0; s < NSC; s++) {
            unsigned sing = __shfl_sync(0xFFFFFFFFu, myf, s) & 0x80000000u;
            float* q = op + s * CC + c4;
            float4 v;
            if (sing) {
                v = *(const float4*)(sSV + s * CC + c4);
            } else {
                float4 h = __ldcs((const float4*)q);
                const float* Ap = sA + s * CC + c4;
                const float* Bp = sB + s * CC + c4;
                v.x = h.x * Ap[0] + Bp[0];
                v.y = h.y * Ap[1] + Bp[1];
                v.z = h.z * Ap[2] + Bp[2];
                v.w = h.w * Ap[3] + Bp[3];
                v.x = v.x > 0.f ? v.x : SLOPEV * v.x;
                v.y = v.y > 0.f ? v.y : SLOPEV * v.y;
                v.z = v.z > 0.f ? v.z : SLOPEV * v.z;
                v.w = v.w > 0.f ? v.w : SLOPEV * v.w;
            }
            __stcs((float4*)q, v);
        }
    }

    // ---- tail cleanup for next replay (extents read from g_nbuckets, which is
    //      cleared only in next call's k_prep -> no intra-kernel ordering hazard) ----
    const unsigned K1 = NSC * NSLOTS / 4;     // keys, uint4 units
    const unsigned K2 = NSC * NSLOTS / 4;     // counts, uint4 units
    unsigned e = (unsigned)g;
    if (e < K1) {
        ((uint4*)g_keys)[e] = make_uint4(0u, 0u, 0u, 0u);
    } else if (e < K1 + K2) {
        ((uint4*)g_counts)[e - K1] = make_uint4(0u, 0u, 0u, 0u);
    } else {
        unsigned r = e - (K1 + K2);
        int nb0 = g_nbuckets[0], nb1 = g_nbuckets[1];
        int nb2 = g_nbuckets[2], nb3 = g_nbuckets[3];
        unsigned n0 = (unsigned)nb0 * 32u, n1 = (unsigned)nb1 * 32u;
        unsigned n2 = (unsigned)nb2 * 32u, n3 = (unsigned)nb3 * 32u;
        float4 z = make_float4(0.f, 0.f, 0.f, 0.f);
        int s; unsigned off;
        if (r < n0)                     { s = 0; off = r; }
        else if (r < n0 + n1)           { s = 1; off = r - n0; }
        else if (r < n0 + n1 + n2)      { s = 2; off = r - n0 - n1; }
        else if (r < n0 + n1 + n2 + n3) { s = 3; off = r - n0 - n1 - n2; }
        else return;
        ((float4*)(g_csums + (size_t)s * MAXB * CC))[off] = z;
    }
}

// ---------------- launcher ----------------
extern "C" void kernel_launch(void* const* d_in, const int* in_sizes, int n_in,
                              void* d_out, int out_size) {
    const float* feats = (const float*)d_in[0];
    const int*   idx   = (const int*)d_in[1];
    const float* W     = (const float*)d_in[2];
    const float* bvec  = (const float*)d_in[3];
    const float* gamma = (const float*)d_in[4];
    const float* beta  = (const float*)d_in[5];
    float* out = (float*)d_out;

    int M = in_sizes[0] / CC;   // 300000

    size_t smem_mma = (size_t)6 * 128 * SP * sizeof(__nv_bfloat16);   // 208896 B
    cudaFuncSetAttribute(k_gemm_all, cudaFuncAttributeMaxDynamicSharedMemorySize,
                         (int)smem_mma);

    int grid_prep  = (NSC * CC * CC + 255) / 256;   // 256
    int grid_pts   = (M + 255) / 256;
    int grid_4     = (M * 4 + 255) / 256;           // 4688 (flagaccum, 4 thr/pt)
    int grid_warp  = (M * 32 + 255) / 256;          // 37500 (norm + tail cleanup)

    dim3 gassign(NSLOTS / 256, NSC);

    k_prep<<<grid_prep, 256>>>(W);
    k_build_all<<<grid_pts, 256>>>(idx, M);
    k_assign<<<gassign, 256>>>();
    k_flagaccum_all<<<grid_4, 256>>>(feats, M);
    k_gemm_all<<<NGB, 256, smem_mma>>>(feats, bvec, out);
    k_finalize_all<<<1, 512>>>(bvec, gamma, beta, M);
    k_norm_all<<<grid_warp, 256>>>(out, M);
}